// round 4
// baseline (speedup 1.0000x reference)
#include <cuda_runtime.h>
#include <cstdint>

#define HEADS 8
#define NBAT  8
#define NTOK  1024
#define NL    3
#define CH    256
#define CPH   32
#define RTOT  (NBAT*NTOK*NL)   // 24576 rows per stream

// ---------------- scratch (device globals: allocation-free) ----------------
// vperm[s][b][h][m][l*32+c] : per (s,b,h) a (1024 x 96) [k][n] matrix, tf32-rounded
__device__ __align__(256) float g_vperm[2u*NBAT*HEADS*NTOK*NL*CPH];
// attout[s][b][n][l*256 + h*32 + c], tf32-rounded
__device__ __align__(256) float g_attout[2u*RTOT*CH];
// rounded weights: [0:64K) = Wv*1.000339 (truncation-bias comp), [64K:128K) = Wo
__device__ __align__(256) float g_W[2*CH*CH];

// ---------------- helpers ----------------
__device__ __forceinline__ uint32_t f2tf32(float x) {
    uint32_t r; asm("cvt.rna.tf32.f32 %0, %1;" : "=r"(r) : "f"(x)); return r;
}
__device__ __forceinline__ void mma8(float* d, const uint32_t* a, const uint32_t* b) {
    asm("mma.sync.aligned.m16n8k8.row.col.f32.tf32.tf32.f32 "
        "{%0,%1,%2,%3}, {%4,%5,%6,%7}, {%8,%9}, {%0,%1,%2,%3};"
        : "+f"(d[0]), "+f"(d[1]), "+f"(d[2]), "+f"(d[3])
        : "r"(a[0]), "r"(a[1]), "r"(a[2]), "r"(a[3]), "r"(b[0]), "r"(b[1]));
}
__device__ __forceinline__ uint32_t elect1() {
    uint32_t p;
    asm volatile("{\n\t.reg .pred p;\n\telect.sync _|p, 0xFFFFFFFF;\n\t"
                 "selp.b32 %0, 1, 0, p;\n\t}" : "=r"(p));
    return p;
}
__device__ __forceinline__ void bulk_g2s(uint32_t dst, const float* src,
                                         uint32_t bytes, uint32_t mbar) {
    asm volatile("cp.async.bulk.shared::cta.global.mbarrier::complete_tx::bytes "
                 "[%0], [%1], %2, [%3];"
                 :: "r"(dst), "l"(src), "r"(bytes), "r"(mbar) : "memory");
}
#define MBAR_INIT(a, c) \
    asm volatile("mbarrier.init.shared.b64 [%0], %1;" :: "r"((uint32_t)(a)), "r"((uint32_t)(c)) : "memory")
#define MBAR_EXPECT(a, b) \
    asm volatile("mbarrier.arrive.expect_tx.shared.b64 _, [%0], %1;" :: "r"((uint32_t)(a)), "r"((uint32_t)(b)) : "memory")
#define MBAR_ARRIVE(a) \
    asm volatile("mbarrier.arrive.shared.b64 _, [%0];" :: "r"((uint32_t)(a)) : "memory")
#define MBAR_WAIT(mb, ph) do { \
    uint32_t _m = (uint32_t)(mb), _p = (uint32_t)(ph), _d; \
    asm volatile("{\n\t.reg .pred p;\n\t" \
        "mbarrier.try_wait.parity.acquire.cta.shared::cta.b64 p, [%1], %2;\n\t" \
        "selp.b32 %0, 1, 0, p;\n\t}" : "=r"(_d) : "r"(_m), "r"(_p) : "memory"); \
    if (!_d) { \
        asm volatile("{\n\t.reg .pred P1;\n\t" \
            "WL_%=:\n\t" \
            "mbarrier.try_wait.parity.acquire.cta.shared::cta.b64 P1, [%0], %1, 0x989680;\n\t" \
            "@P1 bra.uni WD_%=;\n\tbra.uni WL_%=;\n\tWD_%=:\n\t}" \
            :: "r"(_m), "r"(_p) : "memory"); \
    } \
} while(0)

// =====================================================================
// W prep: pre-round weights to tf32. Wv gets *1.000339 (= 1 + 2^-11*ln2):
// cancels mean truncation bias of the raw uniform[0,1) att operand in stage 2.
// =====================================================================
__global__ void wprep_kernel(const float* __restrict__ Wv, const float* __restrict__ Wo) {
    int i = blockIdx.x * 256 + threadIdx.x;
    g_W[i]         = __uint_as_float(f2tf32(Wv[i] * 1.000339f));
    g_W[CH*CH + i] = __uint_as_float(f2tf32(Wo[i]));
}

// =====================================================================
// proj: MODE 0: A=equ_s (cvt.rna), W=Wv' -> g_vperm (rounded, permuted)
//       MODE 1: A=g_attout_s (raw tf32 bits), W=Wo' -> out + residual
// Tile 128x64, BK=32, K=256 -> 8 ksteps. 3-stage bulk+mbarrier pipeline.
// Stage: A 128 rows x 128B (dst stride 144) + W 64 rows x 128B (stride 144).
// =====================================================================
#define P_AOFF  0
#define P_WOFF  (128*144)
#define P_STG   (192*144)          // 27648 B
#define P_TX    (128*128 + 64*128) // 24576 B copied per stage
#define PROJ_SMEM (64 + 3*P_STG)   // 83008 B

template<int MODE>
__global__ void __launch_bounds__(256) proj_kernel(
    const float* __restrict__ equ1, const float* __restrict__ equ2,
    float* __restrict__ out)
{
    extern __shared__ float ps[];
    const uint32_t base = (uint32_t)__cvta_generic_to_shared(ps);
    const uint32_t data = base + 64;
    char* datap = (char*)ps + 64;

    const int s = blockIdx.z;
    const float* A;
    if (MODE == 0) A = s ? equ2 : equ1;
    else           A = g_attout + (size_t)s * RTOT * CH;
    const float* W = (MODE == 0) ? g_W : (g_W + CH*CH);

    const int rbase = blockIdx.x * 128;
    const int jbase = blockIdx.y * 64;
    const int tid  = threadIdx.x;
    const int warp = tid >> 5, lane = tid & 31;
    const int wm = warp >> 1, wn = warp & 1;
    const int g = lane >> 2, tg = lane & 3;

    if (tid == 0) {
        #pragma unroll
        for (int p = 0; p < 3; p++) {
            MBAR_INIT(base + p*8, 1);        // full
            MBAR_INIT(base + 24 + p*8, 8);   // empty
        }
    }
    __syncthreads();

    const float* Ag = A + (size_t)rbase * CH;
    const float* Wg = W + (size_t)jbase * CH;

    auto load_stage = [&](int ks, int st) {   // warp0, all 32 lanes
        const int kb = ks * 32;
        const uint32_t aS = data + st * P_STG;
        const uint32_t mb = base + st*8;
        #pragma unroll
        for (int q = 0; q < 4; q++) {
            int row = lane + q*32;
            bulk_g2s(aS + row*144, Ag + (size_t)row*CH + kb, 128, mb);
        }
        #pragma unroll
        for (int q = 0; q < 2; q++) {
            int row = lane + q*32;
            bulk_g2s(aS + P_WOFF + row*144, Wg + (size_t)row*CH + kb, 128, mb);
        }
    };

    if (warp == 0) {
        #pragma unroll
        for (int p = 0; p < 3; p++) {
            if (elect1()) MBAR_EXPECT(base + p*8, P_TX);
            load_stage(p, p);
        }
    }

    float acc[2][4][4];
    #pragma unroll
    for (int i = 0; i < 2; i++)
        #pragma unroll
        for (int j = 0; j < 4; j++)
            #pragma unroll
            for (int k = 0; k < 4; k++) acc[i][j][k] = 0.f;

    int st = 0;
    for (int ks = 0; ks < 8; ks++) {
        const int ph = (ks / 3) & 1;
        MBAR_WAIT(base + st*8, ph);

        const float* Ad = (const float*)(datap + st*P_STG);
        const float* Wd = (const float*)(datap + st*P_STG + P_WOFF);
        #pragma unroll
        for (int kk = 0; kk < 4; kk++) {
            uint32_t af[2][4];
            #pragma unroll
            for (int mi = 0; mi < 2; mi++) {
                int r = wm*32 + mi*16 + g, c = kk*8 + tg;
                if (MODE == 0) {
                    af[mi][0] = f2tf32(Ad[r*36 + c]);
                    af[mi][1] = f2tf32(Ad[(r+8)*36 + c]);
                    af[mi][2] = f2tf32(Ad[r*36 + c + 4]);
                    af[mi][3] = f2tf32(Ad[(r+8)*36 + c + 4]);
                } else {
                    af[mi][0] = __float_as_uint(Ad[r*36 + c]);
                    af[mi][1] = __float_as_uint(Ad[(r+8)*36 + c]);
                    af[mi][2] = __float_as_uint(Ad[r*36 + c + 4]);
                    af[mi][3] = __float_as_uint(Ad[(r+8)*36 + c + 4]);
                }
            }
            #pragma unroll
            for (int nj = 0; nj < 4; nj++) {
                int j = wn*32 + nj*8 + g, c = kk*8 + tg;
                uint32_t bf[2];
                bf[0] = __float_as_uint(Wd[j*36 + c]);
                bf[1] = __float_as_uint(Wd[j*36 + c + 4]);
                #pragma unroll
                for (int mi = 0; mi < 2; mi++) mma8(acc[mi][nj], af[mi], bf);
            }
        }

        if (elect1()) MBAR_ARRIVE(base + 24 + st*8);
        if (warp == 0 && ks + 3 < 8) {
            MBAR_WAIT(base + 24 + st*8, ph);
            if (elect1()) MBAR_EXPECT(base + st*8, P_TX);
            load_stage(ks + 3, st);
        }
        st++; if (st == 3) st = 0;
    }

    #pragma unroll
    for (int mi = 0; mi < 2; mi++)
        #pragma unroll
        for (int nj = 0; nj < 4; nj++) {
            const int j = jbase + wn*32 + nj*8 + 2*tg;
            #pragma unroll
            for (int half = 0; half < 2; half++) {
                const int r = rbase + wm*32 + mi*16 + g + half*8;
                float2 v = make_float2(acc[mi][nj][half*2], acc[mi][nj][half*2+1]);
                if (MODE == 0) {
                    v.x = __uint_as_float(f2tf32(v.x));
                    v.y = __uint_as_float(f2tf32(v.y));
                    int b = r / 3072, rem = r % 3072;
                    int m = rem / 3, l = rem % 3;
                    int h = j >> 5, c = j & 31;
                    size_t o = (((size_t)((s*NBAT + b)*HEADS + h)*NTOK + m)*(NL*CPH))
                               + l*CPH + c;
                    *(float2*)&g_vperm[o] = v;
                } else {
                    const float* R = s ? equ2 : equ1;
                    size_t o = (size_t)r*CH + j;
                    float2 rr = *(const float2*)&R[o];
                    v.x += rr.x; v.y += rr.y;
                    *(float2*)&out[(size_t)s*RTOT*CH + o] = v;
                }
            }
        }
}

// =====================================================================
// attn: per (s,bh,mt): attout(128 x 96) = att(128x1024) @ vperm(1024x96)
// 3-stage bulk+mbarrier pipeline. A: 128 row-bulks of 128B (dst stride 144);
// B: ONE contiguous 12KB bulk (vperm is [k][96] row-major). 32 ksteps.
// Raw-bit tf32 operands: att HW-truncated (bias folded into Wv'), v pre-rounded.
// =====================================================================
#define AT_ASZ  (128*144)          // 18432 B (padded region)
#define AT_BSZ  (32*96*4)          // 12288 B
#define AT_STG  (AT_ASZ + AT_BSZ)  // 30720 B
#define AT_TX   (128*128 + AT_BSZ) // 28672 B copied per stage
#define ATTN_SMEM (64 + 3*AT_STG)  // 92224 B

__global__ void __launch_bounds__(256) attn_kernel(const float* __restrict__ att)
{
    extern __shared__ float sm[];
    const uint32_t base = (uint32_t)__cvta_generic_to_shared(sm);
    const uint32_t data = base + 64;
    char* datap = (char*)sm + 64;

    const int mt  = blockIdx.x;
    const int bh  = blockIdx.y;
    const int s   = blockIdx.z;
    const int sbh = s*64 + bh;
    const float* ap = att + (size_t)sbh * NTOK * NTOK + (size_t)mt * 128 * NTOK;
    const float* vp = g_vperm + (size_t)sbh * NTOK * (NL*CPH);

    const int tid = threadIdx.x;
    const int warp = tid >> 5, lane = tid & 31;
    const int wm = warp >> 1, wn = warp & 1;
    const int g = lane >> 2, tg = lane & 3;

    if (tid == 0) {
        #pragma unroll
        for (int p = 0; p < 3; p++) {
            MBAR_INIT(base + p*8, 1);        // full
            MBAR_INIT(base + 24 + p*8, 8);   // empty
        }
    }
    __syncthreads();

    auto load_stage = [&](int ks, int st) {   // warp0, all 32 lanes
        const int kb = ks * 32;
        const uint32_t aS = data + st * AT_STG;
        const uint32_t mb = base + st*8;
        #pragma unroll
        for (int q = 0; q < 4; q++) {
            int row = lane + q*32;
            bulk_g2s(aS + row*144, ap + (size_t)row*NTOK + kb, 128, mb);
        }
        if (lane == 0)
            bulk_g2s(aS + AT_ASZ, vp + (size_t)kb*(NL*CPH), AT_BSZ, mb);
    };

    if (warp == 0) {
        #pragma unroll
        for (int p = 0; p < 3; p++) {
            if (elect1()) MBAR_EXPECT(base + p*8, AT_TX);
            load_stage(p, p);
        }
    }

    float acc[2][6][4];
    #pragma unroll
    for (int i = 0; i < 2; i++)
        #pragma unroll
        for (int j = 0; j < 6; j++)
            #pragma unroll
            for (int k = 0; k < 4; k++) acc[i][j][k] = 0.f;

    int st = 0;
    for (int ks = 0; ks < 32; ks++) {
        const int ph = (ks / 3) & 1;
        MBAR_WAIT(base + st*8, ph);

        const float* Ad = (const float*)(datap + st*AT_STG);
        const float* Bd = (const float*)(datap + st*AT_STG + AT_ASZ);
        #pragma unroll
        for (int kk = 0; kk < 4; kk++) {
            uint32_t af[2][4];
            #pragma unroll
            for (int mi = 0; mi < 2; mi++) {
                int r = wm*32 + mi*16 + g, c = kk*8 + tg;
                af[mi][0] = __float_as_uint(Ad[r*36 + c]);
                af[mi][1] = __float_as_uint(Ad[(r+8)*36 + c]);
                af[mi][2] = __float_as_uint(Ad[r*36 + c + 4]);
                af[mi][3] = __float_as_uint(Ad[(r+8)*36 + c + 4]);
            }
            #pragma unroll
            for (int nj = 0; nj < 6; nj++) {
                int j = wn*48 + nj*8 + g, c = kk*8 + tg;
                uint32_t bf[2];
                bf[0] = __float_as_uint(Bd[c*96 + j]);
                bf[1] = __float_as_uint(Bd[(c+4)*96 + j]);
                #pragma unroll
                for (int mi = 0; mi < 2; mi++) mma8(acc[mi][nj], af[mi], bf);
            }
        }

        if (elect1()) MBAR_ARRIVE(base + 24 + st*8);
        if (warp == 0 && ks + 3 < 32) {
            MBAR_WAIT(base + 24 + st*8, ph);
            if (elect1()) MBAR_EXPECT(base + st*8, AT_TX);
            load_stage(ks + 3, st);
        }
        st++; if (st == 3) st = 0;
    }

    // epilogue: round to tf32 (proj1 consumes raw bits) + scatter
    const int b = bh >> 3, h = bh & 7;
    float* op = g_attout + (size_t)(s*NBAT + b) * NTOK * (NL*CH);
    #pragma unroll
    for (int mi = 0; mi < 2; mi++)
        #pragma unroll
        for (int nj = 0; nj < 6; nj++) {
            const int j = wn*48 + nj*8 + 2*tg;
            const int l = j >> 5, c = j & 31;
            #pragma unroll
            for (int half = 0; half < 2; half++) {
                const int row = mt*128 + wm*32 + mi*16 + g + half*8;
                float2 v;
                v.x = __uint_as_float(f2tf32(acc[mi][nj][half*2]));
                v.y = __uint_as_float(f2tf32(acc[mi][nj][half*2+1]));
                *(float2*)&op[(size_t)row*(NL*CH) + l*CH + h*CPH + c] = v;
            }
        }
}

// =====================================================================
extern "C" void kernel_launch(void* const* d_in, const int* in_sizes, int n_in,
                              void* d_out, int out_size)
{
    const float* att  = (const float*)d_in[0];
    const float* equ1 = (const float*)d_in[1];
    const float* equ2 = (const float*)d_in[2];
    const float* Wv   = (const float*)d_in[3];
    const float* Wo   = (const float*)d_in[4];
    float* out = (float*)d_out;

    cudaFuncSetAttribute(proj_kernel<0>, cudaFuncAttributeMaxDynamicSharedMemorySize, PROJ_SMEM);
    cudaFuncSetAttribute(proj_kernel<1>, cudaFuncAttributeMaxDynamicSharedMemorySize, PROJ_SMEM);
    cudaFuncSetAttribute(attn_kernel, cudaFuncAttributeMaxDynamicSharedMemorySize, ATTN_SMEM);

    wprep_kernel<<<CH*CH/256, 256>>>(Wv, Wo);
    proj_kernel<0><<<dim3(RTOT/128, CH/64, 2), 256, PROJ_SMEM>>>(equ1, equ2, nullptr);
    attn_kernel<<<dim3(NTOK/128, NBAT*HEADS, 2), 256, ATTN_SMEM>>>(att);
    proj_kernel<1><<<dim3(RTOT/128, CH/64, 2), 256, PROJ_SMEM>>>(equ1, equ2, out);
}

// round 5
// speedup vs baseline: 4.3543x; 4.3543x over previous
#include <cuda_runtime.h>
#include <cuda_fp16.h>
#include <cstdint>

#define HEADS 8
#define NBAT  8
#define NTOK  1024
#define NL    3
#define CH    256
#define RTOT  (NBAT*NTOK*NL)   // 24576 rows per stream

// ---------------- scratch (device globals: allocation-free) ----------------
// equ in fp16: [s][r=(b,n,l)][256]
__device__ __align__(256) __half g_equh[2u*RTOT*CH];
// v pair-interleaved per (s,b,h): [m/2=512][lc=96][2]  (low half = even m)
__device__ __align__(256) __half g_vph[2u*64u*512u*96u*2u];
// attout fp16: [s][(b,n)][l*256 + h*32 + c]  (768 per row)
__device__ __align__(256) __half g_aoh[2u*NBAT*NTOK*NL*CH];
// weights fp16 row-major [j][256]: [0:64K)=Wv, [64K:128K)=Wo
__device__ __align__(256) __half g_Wh[2*CH*CH];

// ---------------- helpers ----------------
__device__ __forceinline__ void mma16(float* d, const uint32_t* a, const uint32_t* b) {
    asm("mma.sync.aligned.m16n8k16.row.col.f32.f16.f16.f32 "
        "{%0,%1,%2,%3}, {%4,%5,%6,%7}, {%8,%9}, {%0,%1,%2,%3};"
        : "+f"(d[0]), "+f"(d[1]), "+f"(d[2]), "+f"(d[3])
        : "r"(a[0]), "r"(a[1]), "r"(a[2]), "r"(a[3]), "r"(b[0]), "r"(b[1]));
}
// pack (lo, hi) floats into one f16x2 register (lo in low half)
__device__ __forceinline__ uint32_t pack2(float lo, float hi) {
    uint32_t r; asm("cvt.rn.f16x2.f32 %0, %1, %2;" : "=r"(r) : "f"(hi), "f"(lo)); return r;
}
__device__ __forceinline__ void cpa16(uint32_t sdst, const void* gsrc) {
    asm volatile("cp.async.cg.shared.global [%0], [%1], 16;" :: "r"(sdst), "l"(gsrc));
}
#define CP_COMMIT() asm volatile("cp.async.commit_group;")
#define CP_WAIT(n)  asm volatile("cp.async.wait_group %0;" :: "n"(n))

// =====================================================================
// prep: equ -> fp16 (natural layout), W -> fp16
// =====================================================================
__global__ void equh_kernel(const float* __restrict__ e1, const float* __restrict__ e2) {
    const float* src = blockIdx.y ? e2 : e1;
    __half* dst = g_equh + (size_t)blockIdx.y * RTOT * CH;
    size_t i = ((size_t)blockIdx.x * 256 + threadIdx.x) * 4;
    float4 v = *(const float4*)(src + i);
    __half2 h0 = __floats2half2_rn(v.x, v.y);
    __half2 h1 = __floats2half2_rn(v.z, v.w);
    uint2 u;
    u.x = *reinterpret_cast<uint32_t*>(&h0);
    u.y = *reinterpret_cast<uint32_t*>(&h1);
    *reinterpret_cast<uint2*>(dst + i) = u;
}
__global__ void wprep_kernel(const float* __restrict__ Wv, const float* __restrict__ Wo) {
    int i = blockIdx.x * 256 + threadIdx.x;
    g_Wh[i]         = __float2half_rn(Wv[i]);
    g_Wh[CH*CH + i] = __float2half_rn(Wo[i]);
}

// =====================================================================
// proj: MODE 0: A=equh, W=Wv -> g_vph (pair-interleaved scatter)
//       MODE 1: A=g_aoh,  W=Wo -> out f32 + residual
// Tile 128x64, BK=32 (2x k16), K=256 -> 8 ksteps, 3-stage cp.async.
// A smem: 128 rows x 20 u32 (16 data + 4 pad); W: 64 x 20.
// =====================================================================
#define P_ASTR 20
#define P_STGU (128*P_ASTR + 64*P_ASTR)   // 3840 u32 / stage
#define PROJ_SMEM (3*P_STGU*4)            // 46080 B

template<int MODE>
__global__ void __launch_bounds__(256) proj_kernel(
    const float* __restrict__ equ1, const float* __restrict__ equ2,
    float* __restrict__ out)
{
    extern __shared__ uint32_t ps[];
    const uint32_t smem_b = (uint32_t)__cvta_generic_to_shared(ps);

    const int s = blockIdx.z;
    const int rbase = blockIdx.x * 128;
    const int jbase = blockIdx.y * 64;
    const int tid = threadIdx.x;
    const int warp = tid >> 5, lane = tid & 31;
    const int wm = warp >> 1, wn = warp & 1;
    const int g = lane >> 2, tg = lane & 3;

    const __half* Abase = (MODE == 0) ? (g_equh + (size_t)s*RTOT*CH)
                                      : (g_aoh  + (size_t)s*RTOT*CH);
    const __half* Wbase = g_Wh + (MODE ? CH*CH : 0) + (size_t)jbase * CH;

    // per-thread load coords: A 512 chunks (2/thr), W 256 chunks (1/thr)
    const __half* asrc[2]; uint32_t adst[2];
    #pragma unroll
    for (int t = 0; t < 2; t++) {
        int c = tid + t*256;
        int row = c >> 2, off = c & 3;
        int r = rbase + row;
        size_t rofs = (MODE == 0) ? (size_t)r*CH
                                  : (size_t)(r/3)*768 + (size_t)(r%3)*256;
        asrc[t] = Abase + rofs + off*8;
        adst[t] = (uint32_t)(row*P_ASTR + off*4) * 4;
    }
    const __half* wsrc = Wbase + (size_t)(tid >> 2)*CH + (tid & 3)*8;
    const uint32_t wdst = (uint32_t)(128*P_ASTR + (tid >> 2)*P_ASTR + (tid & 3)*4) * 4;

    auto load_stage = [&](int ks, int st) {
        const uint32_t sb = smem_b + st * P_STGU * 4;
        const int kb = ks * 32;
        cpa16(sb + adst[0], asrc[0] + kb);
        cpa16(sb + adst[1], asrc[1] + kb);
        cpa16(sb + wdst, wsrc + kb);
        CP_COMMIT();
    };

    float acc[2][4][4];
    #pragma unroll
    for (int i = 0; i < 2; i++)
        #pragma unroll
        for (int j = 0; j < 4; j++)
            #pragma unroll
            for (int k = 0; k < 4; k++) acc[i][j][k] = 0.f;

    load_stage(0, 0);
    load_stage(1, 1);
    int st = 0;
    for (int ks = 0; ks < 8; ks++) {
        if (ks + 2 < 8) load_stage(ks + 2, (ks + 2) % 3);
        if      (ks <= 5) CP_WAIT(2);
        else if (ks == 6) CP_WAIT(1);
        else              CP_WAIT(0);
        __syncthreads();

        const uint32_t* Ad = ps + st * P_STGU;
        const uint32_t* Wd = Ad + 128*P_ASTR;
        #pragma unroll
        for (int kk = 0; kk < 2; kk++) {
            uint32_t a[2][4];
            #pragma unroll
            for (int mi = 0; mi < 2; mi++) {
                int r = wm*32 + mi*16 + g;
                a[mi][0] = Ad[r*P_ASTR + kk*8 + tg];
                a[mi][1] = Ad[(r+8)*P_ASTR + kk*8 + tg];
                a[mi][2] = Ad[r*P_ASTR + kk*8 + tg + 4];
                a[mi][3] = Ad[(r+8)*P_ASTR + kk*8 + tg + 4];
            }
            #pragma unroll
            for (int nj = 0; nj < 4; nj++) {
                int j = wn*32 + nj*8 + g;
                uint32_t b[2] = { Wd[j*P_ASTR + kk*8 + tg], Wd[j*P_ASTR + kk*8 + tg + 4] };
                #pragma unroll
                for (int mi = 0; mi < 2; mi++) mma16(acc[mi][nj], a[mi], b);
            }
        }
        __syncthreads();
        st++; if (st == 3) st = 0;
    }

    #pragma unroll
    for (int mi = 0; mi < 2; mi++)
        #pragma unroll
        for (int nj = 0; nj < 4; nj++) {
            const int j = jbase + wn*32 + nj*8 + 2*tg;
            #pragma unroll
            for (int half = 0; half < 2; half++) {
                const int r = rbase + wm*32 + mi*16 + g + half*8;
                float v0 = acc[mi][nj][half*2], v1 = acc[mi][nj][half*2+1];
                if (MODE == 0) {
                    // scatter to pair-interleaved vph
                    int b = r / 3072, rem = r % 3072;
                    int m = rem / 3, l = rem % 3;
                    int h = j >> 5, c = j & 31;
                    int sbh = s*64 + b*8 + h;
                    size_t hw = (((size_t)sbh*512 + (m>>1))*96 + l*32 + c)*2 + (m & 1);
                    g_vph[hw]     = __float2half_rn(v0);
                    g_vph[hw + 2] = __float2half_rn(v1);
                } else {
                    const float* R = s ? equ2 : equ1;
                    size_t o = (size_t)r*CH + j;
                    float2 rr = *(const float2*)&R[o];
                    float2 w = make_float2(v0 + rr.x, v1 + rr.y);
                    *(float2*)&out[(size_t)s*RTOT*CH + o] = w;
                }
            }
        }
}

// =====================================================================
// attn: per (s,bh,mt): aoh(128 x 96) = att(128x1024) @ v(1024x96), fp16 MMA
// A: att f32 in smem (stride 36), cvt to f16x2 at frag load.
// B: vph pair-interleaved, smem [16 pairs][104 u32] (stride 104 -> no conflicts)
// 3-stage cp.async, 32 ksteps of BK=32 (2x k16).
// =====================================================================
#define A_STR   36
#define AT_AU   (128*A_STR)       // 4608 u32
#define AT_BU   (16*104)          // 1664 u32
#define AT_STGU (AT_AU + AT_BU)   // 6272 u32 = 25088 B
#define ATTN_SMEM (3*AT_STGU*4)   // 75264 B

__global__ void __launch_bounds__(256, 2) attn_kernel(const float* __restrict__ att)
{
    extern __shared__ uint32_t sm[];
    const uint32_t smem_b = (uint32_t)__cvta_generic_to_shared(sm);

    const int mt  = blockIdx.x;
    const int bh  = blockIdx.y;
    const int s   = blockIdx.z;
    const int sbh = s*64 + bh;
    const float* ap = att + (size_t)sbh * NTOK * NTOK + (size_t)mt * 128 * NTOK;
    const uint32_t* vp = (const uint32_t*)g_vph + (size_t)sbh * 512 * 96;

    const int tid = threadIdx.x;
    const int warp = tid >> 5, lane = tid & 31;
    const int wm = warp >> 1, wn = warp & 1;
    const int g = lane >> 2, tg = lane & 3;

    // A: 1024 chunks (4/thr); B: 384 chunks (2 for tid<128, else 1)
    const float* asrcp[4]; uint32_t adst[4];
    #pragma unroll
    for (int t = 0; t < 4; t++) {
        int c = tid + t*256;
        int row = c >> 3, off = c & 7;
        asrcp[t] = ap + (size_t)row*NTOK + off*4;
        adst[t] = (uint32_t)(row*A_STR + off*4) * 4;
    }
    const uint32_t* bsrcp[2]; uint32_t bdst[2]; bool bval[2];
    #pragma unroll
    for (int t = 0; t < 2; t++) {
        int c = tid + t*256;
        bval[t] = (c < 384);
        int pair = c / 24, off = c % 24;
        bsrcp[t] = vp + pair*96 + off*4;
        bdst[t] = (uint32_t)(AT_AU + pair*104 + off*4) * 4;
    }

    auto load_stage = [&](int ks, int st) {
        const uint32_t sb = smem_b + st * AT_STGU * 4;
        const int kb = ks * 32;
        #pragma unroll
        for (int t = 0; t < 4; t++) cpa16(sb + adst[t], asrcp[t] + kb);
        const int bofs = ks * 16 * 96;   // u32
        #pragma unroll
        for (int t = 0; t < 2; t++)
            if (bval[t]) cpa16(sb + bdst[t], bsrcp[t] + bofs);
        CP_COMMIT();
    };

    float acc[2][6][4];
    #pragma unroll
    for (int i = 0; i < 2; i++)
        #pragma unroll
        for (int j = 0; j < 6; j++)
            #pragma unroll
            for (int k = 0; k < 4; k++) acc[i][j][k] = 0.f;

    load_stage(0, 0);
    load_stage(1, 1);
    int st = 0;
    for (int ks = 0; ks < 32; ks++) {
        if (ks + 2 < 32) load_stage(ks + 2, (ks + 2) % 3);
        if      (ks <= 29) CP_WAIT(2);
        else if (ks == 30) CP_WAIT(1);
        else               CP_WAIT(0);
        __syncthreads();

        const float* Adf = (const float*)(sm + st * AT_STGU);
        const uint32_t* Bd = sm + st * AT_STGU + AT_AU;
        #pragma unroll
        for (int kk = 0; kk < 2; kk++) {
            uint32_t a[2][4];
            #pragma unroll
            for (int mi = 0; mi < 2; mi++) {
                int r = wm*32 + mi*16 + g;
                float2 p0 = *(const float2*)(Adf + r*A_STR + kk*16 + 2*tg);
                float2 p1 = *(const float2*)(Adf + (r+8)*A_STR + kk*16 + 2*tg);
                float2 p2 = *(const float2*)(Adf + r*A_STR + kk*16 + 2*tg + 8);
                float2 p3 = *(const float2*)(Adf + (r+8)*A_STR + kk*16 + 2*tg + 8);
                a[mi][0] = pack2(p0.x, p0.y);
                a[mi][1] = pack2(p1.x, p1.y);
                a[mi][2] = pack2(p2.x, p2.y);
                a[mi][3] = pack2(p3.x, p3.y);
            }
            #pragma unroll
            for (int nj = 0; nj < 6; nj++) {
                int j = wn*48 + nj*8 + g;
                uint32_t b[2] = { Bd[(kk*8 + tg)*104 + j], Bd[(kk*8 + tg + 4)*104 + j] };
                #pragma unroll
                for (int mi = 0; mi < 2; mi++) mma16(acc[mi][nj], a[mi], b);
            }
        }
        __syncthreads();
        st++; if (st == 3) st = 0;
    }

    // epilogue: pack fp16 pairs (cols j,j+1 = pairs along proj1's K) + scatter
    const int b = bh >> 3, h = bh & 7;
    uint32_t* aop = (uint32_t*)g_aoh + ((size_t)(s*NBAT + b) * NTOK) * 384;
    #pragma unroll
    for (int mi = 0; mi < 2; mi++)
        #pragma unroll
        for (int nj = 0; nj < 6; nj++) {
            const int j = wn*48 + nj*8 + 2*tg;
            const int l = j >> 5, c = j & 31;
            #pragma unroll
            for (int half = 0; half < 2; half++) {
                const int row = mt*128 + wm*32 + mi*16 + g + half*8;
                uint32_t v = pack2(acc[mi][nj][half*2], acc[mi][nj][half*2+1]);
                aop[(size_t)row*384 + l*128 + h*16 + (c >> 1)] = v;
            }
        }
}

// =====================================================================
extern "C" void kernel_launch(void* const* d_in, const int* in_sizes, int n_in,
                              void* d_out, int out_size)
{
    const float* att  = (const float*)d_in[0];
    const float* equ1 = (const float*)d_in[1];
    const float* equ2 = (const float*)d_in[2];
    const float* Wv   = (const float*)d_in[3];
    const float* Wo   = (const float*)d_in[4];
    float* out = (float*)d_out;

    cudaFuncSetAttribute(proj_kernel<0>, cudaFuncAttributeMaxDynamicSharedMemorySize, PROJ_SMEM);
    cudaFuncSetAttribute(proj_kernel<1>, cudaFuncAttributeMaxDynamicSharedMemorySize, PROJ_SMEM);
    cudaFuncSetAttribute(attn_kernel, cudaFuncAttributeMaxDynamicSharedMemorySize, ATTN_SMEM);

    equh_kernel<<<dim3(RTOT*CH/1024, 2), 256>>>(equ1, equ2);
    wprep_kernel<<<CH*CH/256, 256>>>(Wv, Wo);
    proj_kernel<0><<<dim3(RTOT/128, CH/64, 2), 256, PROJ_SMEM>>>(equ1, equ2, nullptr);
    attn_kernel<<<dim3(NTOK/128, NBAT*HEADS, 2), 256, ATTN_SMEM>>>(att);
    proj_kernel<1><<<dim3(RTOT/128, CH/64, 2), 256, PROJ_SMEM>>>(equ1, equ2, out);
}

// round 6
// speedup vs baseline: 4.3554x; 1.0002x over previous
#include <cuda_runtime.h>
#include <cuda_fp16.h>
#include <cstdint>

#define HEADS 8
#define NBAT  8
#define NTOK  1024
#define NL    3
#define CH    256
#define RTOT  (NBAT*NTOK*NL)   // 24576 rows per stream

// ---------------- scratch (device globals: allocation-free) ----------------
// equ in fp16: [s][r=(b,n,l)][256]
__device__ __align__(256) __half g_equh[2u*RTOT*CH];
// v pair-interleaved per (s,b,h): [m/2=512][lc=96][2]  (low half = even m)
__device__ __align__(256) __half g_vph[2u*64u*512u*96u*2u];
// attout fp16: [s][(b,n)][l*256 + h*32 + c]  (768 per row)
__device__ __align__(256) __half g_aoh[2u*NBAT*NTOK*NL*CH];
// weights fp16 row-major [j][256]: [0:64K)=Wv, [64K:128K)=Wo
__device__ __align__(256) __half g_Wh[2*CH*CH];

// ---------------- helpers ----------------
__device__ __forceinline__ void mma16(float* d, const uint32_t* a, const uint32_t* b) {
    asm("mma.sync.aligned.m16n8k16.row.col.f32.f16.f16.f32 "
        "{%0,%1,%2,%3}, {%4,%5,%6,%7}, {%8,%9}, {%0,%1,%2,%3};"
        : "+f"(d[0]), "+f"(d[1]), "+f"(d[2]), "+f"(d[3])
        : "r"(a[0]), "r"(a[1]), "r"(a[2]), "r"(a[3]), "r"(b[0]), "r"(b[1]));
}
// pack (lo, hi) floats into one f16x2 register (lo in low half)
__device__ __forceinline__ uint32_t pack2(float lo, float hi) {
    uint32_t r; asm("cvt.rn.f16x2.f32 %0, %1, %2;" : "=r"(r) : "f"(hi), "f"(lo)); return r;
}
__device__ __forceinline__ void cpa16(uint32_t sdst, const void* gsrc) {
    asm volatile("cp.async.cg.shared.global [%0], [%1], 16;" :: "r"(sdst), "l"(gsrc));
}
#define CP_COMMIT() asm volatile("cp.async.commit_group;")
#define CP_WAIT(n)  asm volatile("cp.async.wait_group %0;" :: "n"(n))

// =====================================================================
// prep: equ -> fp16 (natural layout), W -> fp16
// =====================================================================
__global__ void equh_kernel(const float* __restrict__ e1, const float* __restrict__ e2) {
    const float* src = blockIdx.y ? e2 : e1;
    __half* dst = g_equh + (size_t)blockIdx.y * RTOT * CH;
    size_t i = ((size_t)blockIdx.x * 256 + threadIdx.x) * 4;
    float4 v = *(const float4*)(src + i);
    __half2 h0 = __floats2half2_rn(v.x, v.y);
    __half2 h1 = __floats2half2_rn(v.z, v.w);
    uint2 u;
    u.x = *reinterpret_cast<uint32_t*>(&h0);
    u.y = *reinterpret_cast<uint32_t*>(&h1);
    *reinterpret_cast<uint2*>(dst + i) = u;
}
__global__ void wprep_kernel(const float* __restrict__ Wv, const float* __restrict__ Wo) {
    int i = blockIdx.x * 256 + threadIdx.x;
    g_Wh[i]         = __float2half_rn(Wv[i]);
    g_Wh[CH*CH + i] = __float2half_rn(Wo[i]);
}

// =====================================================================
// proj: MODE 0: A=equh, W=Wv -> g_vph (pair-interleaved scatter)
//       MODE 1: A=g_aoh,  W=Wo -> out f32 + residual
// Tile 128x64, BK=32 (2x k16), K=256 -> 8 ksteps, 3-stage cp.async.
// A smem: 128 rows x 20 u32 (16 data + 4 pad); W: 64 x 20.
// =====================================================================
#define P_ASTR 20
#define P_STGU (128*P_ASTR + 64*P_ASTR)   // 3840 u32 / stage
#define PROJ_SMEM (3*P_STGU*4)            // 46080 B

template<int MODE>
__global__ void __launch_bounds__(256) proj_kernel(
    const float* __restrict__ equ1, const float* __restrict__ equ2,
    float* __restrict__ out)
{
    extern __shared__ uint32_t ps[];
    const uint32_t smem_b = (uint32_t)__cvta_generic_to_shared(ps);

    const int s = blockIdx.z;
    const int rbase = blockIdx.x * 128;
    const int jbase = blockIdx.y * 64;
    const int tid = threadIdx.x;
    const int warp = tid >> 5, lane = tid & 31;
    const int wm = warp >> 1, wn = warp & 1;
    const int g = lane >> 2, tg = lane & 3;

    const __half* Abase = (MODE == 0) ? (g_equh + (size_t)s*RTOT*CH)
                                      : (g_aoh  + (size_t)s*RTOT*CH);
    const __half* Wbase = g_Wh + (MODE ? CH*CH : 0) + (size_t)jbase * CH;

    // per-thread load coords: A 512 chunks (2/thr), W 256 chunks (1/thr)
    const __half* asrc[2]; uint32_t adst[2];
    #pragma unroll
    for (int t = 0; t < 2; t++) {
        int c = tid + t*256;
        int row = c >> 2, off = c & 3;
        int r = rbase + row;
        size_t rofs = (MODE == 0) ? (size_t)r*CH
                                  : (size_t)(r/3)*768 + (size_t)(r%3)*256;
        asrc[t] = Abase + rofs + off*8;
        adst[t] = (uint32_t)(row*P_ASTR + off*4) * 4;
    }
    const __half* wsrc = Wbase + (size_t)(tid >> 2)*CH + (tid & 3)*8;
    const uint32_t wdst = (uint32_t)(128*P_ASTR + (tid >> 2)*P_ASTR + (tid & 3)*4) * 4;

    auto load_stage = [&](int ks, int st) {
        const uint32_t sb = smem_b + st * P_STGU * 4;
        const int kb = ks * 32;
        cpa16(sb + adst[0], asrc[0] + kb);
        cpa16(sb + adst[1], asrc[1] + kb);
        cpa16(sb + wdst, wsrc + kb);
        CP_COMMIT();
    };

    float acc[2][4][4];
    #pragma unroll
    for (int i = 0; i < 2; i++)
        #pragma unroll
        for (int j = 0; j < 4; j++)
            #pragma unroll
            for (int k = 0; k < 4; k++) acc[i][j][k] = 0.f;

    load_stage(0, 0);
    load_stage(1, 1);
    int st = 0;
    for (int ks = 0; ks < 8; ks++) {
        if (ks + 2 < 8) load_stage(ks + 2, (ks + 2) % 3);
        if      (ks <= 5) CP_WAIT(2);
        else if (ks == 6) CP_WAIT(1);
        else              CP_WAIT(0);
        __syncthreads();

        const uint32_t* Ad = ps + st * P_STGU;
        const uint32_t* Wd = Ad + 128*P_ASTR;
        #pragma unroll
        for (int kk = 0; kk < 2; kk++) {
            uint32_t a[2][4];
            #pragma unroll
            for (int mi = 0; mi < 2; mi++) {
                int r = wm*32 + mi*16 + g;
                a[mi][0] = Ad[r*P_ASTR + kk*8 + tg];
                a[mi][1] = Ad[(r+8)*P_ASTR + kk*8 + tg];
                a[mi][2] = Ad[r*P_ASTR + kk*8 + tg + 4];
                a[mi][3] = Ad[(r+8)*P_ASTR + kk*8 + tg + 4];
            }
            #pragma unroll
            for (int nj = 0; nj < 4; nj++) {
                int j = wn*32 + nj*8 + g;
                uint32_t b[2] = { Wd[j*P_ASTR + kk*8 + tg], Wd[j*P_ASTR + kk*8 + tg + 4] };
                #pragma unroll
                for (int mi = 0; mi < 2; mi++) mma16(acc[mi][nj], a[mi], b);
            }
        }
        __syncthreads();
        st++; if (st == 3) st = 0;
    }

    #pragma unroll
    for (int mi = 0; mi < 2; mi++)
        #pragma unroll
        for (int nj = 0; nj < 4; nj++) {
            const int j = jbase + wn*32 + nj*8 + 2*tg;
            #pragma unroll
            for (int half = 0; half < 2; half++) {
                const int r = rbase + wm*32 + mi*16 + g + half*8;
                float v0 = acc[mi][nj][half*2], v1 = acc[mi][nj][half*2+1];
                if (MODE == 0) {
                    // scatter to pair-interleaved vph
                    int b = r / 3072, rem = r % 3072;
                    int m = rem / 3, l = rem % 3;
                    int h = j >> 5, c = j & 31;
                    int sbh = s*64 + b*8 + h;
                    size_t hw = (((size_t)sbh*512 + (m>>1))*96 + l*32 + c)*2 + (m & 1);
                    g_vph[hw]     = __float2half_rn(v0);
                    g_vph[hw + 2] = __float2half_rn(v1);
                } else {
                    const float* R = s ? equ2 : equ1;
                    size_t o = (size_t)r*CH + j;
                    float2 rr = *(const float2*)&R[o];
                    float2 w = make_float2(v0 + rr.x, v1 + rr.y);
                    *(float2*)&out[(size_t)s*RTOT*CH + o] = w;
                }
            }
        }
}

// =====================================================================
// attn: per (s,bh,mt): aoh(128 x 96) = att(128x1024) @ v(1024x96), fp16 MMA
// A: att f32 in smem (stride 36), cvt to f16x2 at frag load.
// B: vph pair-interleaved, smem [16 pairs][104 u32] (stride 104 -> no conflicts)
// 3-stage cp.async, 32 ksteps of BK=32 (2x k16).
// =====================================================================
#define A_STR   36
#define AT_AU   (128*A_STR)       // 4608 u32
#define AT_BU   (16*104)          // 1664 u32
#define AT_STGU (AT_AU + AT_BU)   // 6272 u32 = 25088 B
#define ATTN_SMEM (3*AT_STGU*4)   // 75264 B

__global__ void __launch_bounds__(256, 2) attn_kernel(const float* __restrict__ att)
{
    extern __shared__ uint32_t sm[];
    const uint32_t smem_b = (uint32_t)__cvta_generic_to_shared(sm);

    const int mt  = blockIdx.x;
    const int bh  = blockIdx.y;
    const int s   = blockIdx.z;
    const int sbh = s*64 + bh;
    const float* ap = att + (size_t)sbh * NTOK * NTOK + (size_t)mt * 128 * NTOK;
    const uint32_t* vp = (const uint32_t*)g_vph + (size_t)sbh * 512 * 96;

    const int tid = threadIdx.x;
    const int warp = tid >> 5, lane = tid & 31;
    const int wm = warp >> 1, wn = warp & 1;
    const int g = lane >> 2, tg = lane & 3;

    // A: 1024 chunks (4/thr); B: 384 chunks (2 for tid<128, else 1)
    const float* asrcp[4]; uint32_t adst[4];
    #pragma unroll
    for (int t = 0; t < 4; t++) {
        int c = tid + t*256;
        int row = c >> 3, off = c & 7;
        asrcp[t] = ap + (size_t)row*NTOK + off*4;
        adst[t] = (uint32_t)(row*A_STR + off*4) * 4;
    }
    const uint32_t* bsrcp[2]; uint32_t bdst[2]; bool bval[2];
    #pragma unroll
    for (int t = 0; t < 2; t++) {
        int c = tid + t*256;
        bval[t] = (c < 384);
        int pair = c / 24, off = c % 24;
        bsrcp[t] = vp + pair*96 + off*4;
        bdst[t] = (uint32_t)(AT_AU + pair*104 + off*4) * 4;
    }

    auto load_stage = [&](int ks, int st) {
        const uint32_t sb = smem_b + st * AT_STGU * 4;
        const int kb = ks * 32;
        #pragma unroll
        for (int t = 0; t < 4; t++) cpa16(sb + adst[t], asrcp[t] + kb);
        const int bofs = ks * 16 * 96;   // u32
        #pragma unroll
        for (int t = 0; t < 2; t++)
            if (bval[t]) cpa16(sb + bdst[t], bsrcp[t] + bofs);
        CP_COMMIT();
    };

    float acc[2][6][4];
    #pragma unroll
    for (int i = 0; i < 2; i++)
        #pragma unroll
        for (int j = 0; j < 6; j++)
            #pragma unroll
            for (int k = 0; k < 4; k++) acc[i][j][k] = 0.f;

    load_stage(0, 0);
    load_stage(1, 1);
    int st = 0;
    for (int ks = 0; ks < 32; ks++) {
        if (ks + 2 < 32) load_stage(ks + 2, (ks + 2) % 3);
        if      (ks <= 29) CP_WAIT(2);
        else if (ks == 30) CP_WAIT(1);
        else               CP_WAIT(0);
        __syncthreads();

        const float* Adf = (const float*)(sm + st * AT_STGU);
        const uint32_t* Bd = sm + st * AT_STGU + AT_AU;
        #pragma unroll
        for (int kk = 0; kk < 2; kk++) {
            uint32_t a[2][4];
            #pragma unroll
            for (int mi = 0; mi < 2; mi++) {
                int r = wm*32 + mi*16 + g;
                float2 p0 = *(const float2*)(Adf + r*A_STR + kk*16 + 2*tg);
                float2 p1 = *(const float2*)(Adf + (r+8)*A_STR + kk*16 + 2*tg);
                float2 p2 = *(const float2*)(Adf + r*A_STR + kk*16 + 2*tg + 8);
                float2 p3 = *(const float2*)(Adf + (r+8)*A_STR + kk*16 + 2*tg + 8);
                a[mi][0] = pack2(p0.x, p0.y);
                a[mi][1] = pack2(p1.x, p1.y);
                a[mi][2] = pack2(p2.x, p2.y);
                a[mi][3] = pack2(p3.x, p3.y);
            }
            #pragma unroll
            for (int nj = 0; nj < 6; nj++) {
                int j = wn*48 + nj*8 + g;
                uint32_t b[2] = { Bd[(kk*8 + tg)*104 + j], Bd[(kk*8 + tg + 4)*104 + j] };
                #pragma unroll
                for (int mi = 0; mi < 2; mi++) mma16(acc[mi][nj], a[mi], b);
            }
        }
        __syncthreads();
        st++; if (st == 3) st = 0;
    }

    // epilogue: pack fp16 pairs (cols j,j+1 = pairs along proj1's K) + scatter
    const int b = bh >> 3, h = bh & 7;
    uint32_t* aop = (uint32_t*)g_aoh + ((size_t)(s*NBAT + b) * NTOK) * 384;
    #pragma unroll
    for (int mi = 0; mi < 2; mi++)
        #pragma unroll
        for (int nj = 0; nj < 6; nj++) {
            const int j = wn*48 + nj*8 + 2*tg;
            const int l = j >> 5, c = j & 31;
            #pragma unroll
            for (int half = 0; half < 2; half++) {
                const int row = mt*128 + wm*32 + mi*16 + g + half*8;
                uint32_t v = pack2(acc[mi][nj][half*2], acc[mi][nj][half*2+1]);
                aop[(size_t)row*384 + l*128 + h*16 + (c >> 1)] = v;
            }
        }
}

// =====================================================================
extern "C" void kernel_launch(void* const* d_in, const int* in_sizes, int n_in,
                              void* d_out, int out_size)
{
    const float* att  = (const float*)d_in[0];
    const float* equ1 = (const float*)d_in[1];
    const float* equ2 = (const float*)d_in[2];
    const float* Wv   = (const float*)d_in[3];
    const float* Wo   = (const float*)d_in[4];
    float* out = (float*)d_out;

    cudaFuncSetAttribute(proj_kernel<0>, cudaFuncAttributeMaxDynamicSharedMemorySize, PROJ_SMEM);
    cudaFuncSetAttribute(proj_kernel<1>, cudaFuncAttributeMaxDynamicSharedMemorySize, PROJ_SMEM);
    cudaFuncSetAttribute(attn_kernel, cudaFuncAttributeMaxDynamicSharedMemorySize, ATTN_SMEM);

    equh_kernel<<<dim3(RTOT*CH/1024, 2), 256>>>(equ1, equ2);
    wprep_kernel<<<CH*CH/256, 256>>>(Wv, Wo);
    proj_kernel<0><<<dim3(RTOT/128, CH/64, 2), 256, PROJ_SMEM>>>(equ1, equ2, nullptr);
    attn_kernel<<<dim3(NTOK/128, NBAT*HEADS, 2), 256, ATTN_SMEM>>>(att);
    proj_kernel<1><<<dim3(RTOT/128, CH/64, 2), 256, PROJ_SMEM>>>(equ1, equ2, out);
}

// round 7
// speedup vs baseline: 4.5328x; 1.0407x over previous
#include <cuda.h>
#include <cuda_runtime.h>
#include <cuda_fp16.h>
#include <cstdint>

#define HEADS 8
#define NBAT  8
#define NTOK  1024
#define NL    3
#define CH    256
#define RTOT  (NBAT*NTOK*NL)   // 24576 rows per stream

// ---------------- scratch (device globals: allocation-free) ----------------
// v pair-interleaved per (s,b,h): [m/2=512][lc=96][2]  (low half = even m)
__device__ __align__(256) __half g_vph[2u*64u*512u*96u*2u];
// attout fp16: [s][(b,n)][l*256 + h*32 + c]  (768 per row)
__device__ __align__(256) __half g_aoh[2u*NBAT*NTOK*NL*CH];
// weights fp16 row-major [j][256]: [0:64K)=Wv, [64K:128K)=Wo
__device__ __align__(256) __half g_Wh[2*CH*CH];

// ---------------- helpers ----------------
__device__ __forceinline__ void mma16(float* d, const uint32_t* a, const uint32_t* b) {
    asm("mma.sync.aligned.m16n8k16.row.col.f32.f16.f16.f32 "
        "{%0,%1,%2,%3}, {%4,%5,%6,%7}, {%8,%9}, {%0,%1,%2,%3};"
        : "+f"(d[0]), "+f"(d[1]), "+f"(d[2]), "+f"(d[3])
        : "r"(a[0]), "r"(a[1]), "r"(a[2]), "r"(a[3]), "r"(b[0]), "r"(b[1]));
}
__device__ __forceinline__ uint32_t pack2(float lo, float hi) {
    uint32_t r; asm("cvt.rn.f16x2.f32 %0, %1, %2;" : "=r"(r) : "f"(hi), "f"(lo)); return r;
}
__device__ __forceinline__ void cpa16(uint32_t sdst, const void* gsrc) {
    asm volatile("cp.async.cg.shared.global [%0], [%1], 16;" :: "r"(sdst), "l"(gsrc));
}
#define CP_COMMIT() asm volatile("cp.async.commit_group;")
#define CP_WAIT(n)  asm volatile("cp.async.wait_group %0;" :: "n"(n))
#define MBAR_INIT(a, c) \
    asm volatile("mbarrier.init.shared.b64 [%0], %1;" :: "r"((uint32_t)(a)), "r"((uint32_t)(c)) : "memory")
#define MBAR_EXPECT(a, b) \
    asm volatile("mbarrier.arrive.expect_tx.shared.b64 _, [%0], %1;" :: "r"((uint32_t)(a)), "r"((uint32_t)(b)) : "memory")
#define MBAR_WAIT(mb, ph) do { \
    uint32_t _m = (uint32_t)(mb), _p = (uint32_t)(ph), _d; \
    asm volatile("{\n\t.reg .pred p;\n\t" \
        "mbarrier.try_wait.parity.acquire.cta.shared::cta.b64 p, [%1], %2;\n\t" \
        "selp.b32 %0, 1, 0, p;\n\t}" : "=r"(_d) : "r"(_m), "r"(_p) : "memory"); \
    if (!_d) { \
        asm volatile("{\n\t.reg .pred P1;\n\t" \
            "WL_%=:\n\t" \
            "mbarrier.try_wait.parity.acquire.cta.shared::cta.b64 P1, [%0], %1, 0x989680;\n\t" \
            "@P1 bra.uni WD_%=;\n\tbra.uni WL_%=;\n\tWD_%=:\n\t}" \
            :: "r"(_m), "r"(_p) : "memory"); \
    } \
} while(0)

// =====================================================================
// W prep: fp16 weights
// =====================================================================
__global__ void wprep_kernel(const float* __restrict__ Wv, const float* __restrict__ Wo) {
    int i = blockIdx.x * 256 + threadIdx.x;
    g_Wh[i]         = __float2half_rn(Wv[i]);
    g_Wh[CH*CH + i] = __float2half_rn(Wo[i]);
}

// =====================================================================
// proj: MODE 0: A=equ f32 (cvt at frag load), W=Wv -> g_vph (pair scatter)
//       MODE 1: A=g_aoh fp16,                W=Wo -> out f32 + residual
// Tile 128x64, BK=32 (2x k16), K=256 -> 8 ksteps, 3-stage cp.async.
// =====================================================================
template<int MODE>
__global__ void __launch_bounds__(256, 3) proj_kernel(
    const float* __restrict__ equ1, const float* __restrict__ equ2,
    float* __restrict__ out)
{
    constexpr int ASTR = (MODE == 0) ? 36 : 20;   // u32 per A row in smem
    constexpr int STGU = 128*ASTR + 64*20;        // u32 per stage

    extern __shared__ uint32_t ps[];
    const uint32_t smem_b = (uint32_t)__cvta_generic_to_shared(ps);

    const int s = blockIdx.z;
    const int rbase = blockIdx.x * 128;
    const int jbase = blockIdx.y * 64;
    const int tid = threadIdx.x;
    const int warp = tid >> 5, lane = tid & 31;
    const int wm = warp >> 1, wn = warp & 1;
    const int g = lane >> 2, tg = lane & 3;

    const __half* Wbase = g_Wh + (MODE ? CH*CH : 0) + (size_t)jbase * CH;

    // A load coords
    const float* asrcf[4];
    const __half* asrch[2];
    uint32_t adst[4];
    if constexpr (MODE == 0) {
        const float* Af = (s ? equ2 : equ1) + (size_t)rbase * CH;
        #pragma unroll
        for (int t = 0; t < 4; t++) {
            int c = tid + t*256;
            int row = c >> 3, off = c & 7;
            asrcf[t] = Af + (size_t)row*CH + off*4;
            adst[t] = (uint32_t)(row*ASTR + off*4) * 4;
        }
    } else {
        const __half* Ah = g_aoh + (size_t)s * RTOT * CH;
        #pragma unroll
        for (int t = 0; t < 2; t++) {
            int c = tid + t*256;
            int row = c >> 2, off = c & 3;
            int r = rbase + row;
            size_t rofs = (size_t)(r/3)*768 + (size_t)(r%3)*256;
            asrch[t] = Ah + rofs + off*8;
            adst[t] = (uint32_t)(row*ASTR + off*4) * 4;
        }
    }
    const __half* wsrc = Wbase + (size_t)(tid >> 2)*CH + (tid & 3)*8;
    const uint32_t wdst = (uint32_t)(128*ASTR + (tid >> 2)*20 + (tid & 3)*4) * 4;

    auto load_stage = [&](int ks, int st) {
        const uint32_t sb = smem_b + st * STGU * 4;
        const int kb = ks * 32;
        if constexpr (MODE == 0) {
            #pragma unroll
            for (int t = 0; t < 4; t++) cpa16(sb + adst[t], asrcf[t] + kb);
        } else {
            #pragma unroll
            for (int t = 0; t < 2; t++) cpa16(sb + adst[t], asrch[t] + kb);
        }
        cpa16(sb + wdst, wsrc + kb);
        CP_COMMIT();
    };

    float acc[2][4][4];
    #pragma unroll
    for (int i = 0; i < 2; i++)
        #pragma unroll
        for (int j = 0; j < 4; j++)
            #pragma unroll
            for (int k = 0; k < 4; k++) acc[i][j][k] = 0.f;

    load_stage(0, 0);
    load_stage(1, 1);
    int st = 0;
    for (int ks = 0; ks < 8; ks++) {
        if (ks + 2 < 8) load_stage(ks + 2, (ks + 2) % 3);
        if      (ks <= 5) CP_WAIT(2);
        else if (ks == 6) CP_WAIT(1);
        else              CP_WAIT(0);
        __syncthreads();

        const uint32_t* Ad = ps + st * STGU;
        const uint32_t* Wd = Ad + 128*ASTR;
        #pragma unroll
        for (int kk = 0; kk < 2; kk++) {
            uint32_t a[2][4];
            #pragma unroll
            for (int mi = 0; mi < 2; mi++) {
                int r = wm*32 + mi*16 + g;
                if constexpr (MODE == 0) {
                    const float* Adf = (const float*)Ad;
                    float2 p0 = *(const float2*)(Adf + r*ASTR + kk*16 + 2*tg);
                    float2 p1 = *(const float2*)(Adf + (r+8)*ASTR + kk*16 + 2*tg);
                    float2 p2 = *(const float2*)(Adf + r*ASTR + kk*16 + 2*tg + 8);
                    float2 p3 = *(const float2*)(Adf + (r+8)*ASTR + kk*16 + 2*tg + 8);
                    a[mi][0] = pack2(p0.x, p0.y);
                    a[mi][1] = pack2(p1.x, p1.y);
                    a[mi][2] = pack2(p2.x, p2.y);
                    a[mi][3] = pack2(p3.x, p3.y);
                } else {
                    a[mi][0] = Ad[r*ASTR + kk*8 + tg];
                    a[mi][1] = Ad[(r+8)*ASTR + kk*8 + tg];
                    a[mi][2] = Ad[r*ASTR + kk*8 + tg + 4];
                    a[mi][3] = Ad[(r+8)*ASTR + kk*8 + tg + 4];
                }
            }
            #pragma unroll
            for (int nj = 0; nj < 4; nj++) {
                int j = wn*32 + nj*8 + g;
                uint32_t b[2] = { Wd[j*20 + kk*8 + tg], Wd[j*20 + kk*8 + tg + 4] };
                #pragma unroll
                for (int mi = 0; mi < 2; mi++) mma16(acc[mi][nj], a[mi], b);
            }
        }
        __syncthreads();
        st++; if (st == 3) st = 0;
    }

    #pragma unroll
    for (int mi = 0; mi < 2; mi++)
        #pragma unroll
        for (int nj = 0; nj < 4; nj++) {
            const int j = jbase + wn*32 + nj*8 + 2*tg;
            #pragma unroll
            for (int half = 0; half < 2; half++) {
                const int r = rbase + wm*32 + mi*16 + g + half*8;
                float v0 = acc[mi][nj][half*2], v1 = acc[mi][nj][half*2+1];
                if (MODE == 0) {
                    int b = r / 3072, rem = r % 3072;
                    int m = rem / 3, l = rem % 3;
                    int h = j >> 5, c = j & 31;
                    int sbh = s*64 + b*8 + h;
                    size_t hw = (((size_t)sbh*512 + (m>>1))*96 + l*32 + c)*2 + (m & 1);
                    g_vph[hw]     = __float2half_rn(v0);
                    g_vph[hw + 2] = __float2half_rn(v1);
                } else {
                    const float* R = s ? equ2 : equ1;
                    size_t o = (size_t)r*CH + j;
                    float2 rr = *(const float2*)&R[o];
                    float2 w = make_float2(v0 + rr.x, v1 + rr.y);
                    *(float2*)&out[(size_t)s*RTOT*CH + o] = w;
                }
            }
        }
}

// =====================================================================
// attn: per (s,bh,mt): aoh(128 x 96) = att(128x1024) @ v(1024x96), fp16 MMA
// A: 2D TMA (box 32x128 f32, SW128) -> one UTMALDG per stage, mbarrier tx.
//    Frag loads apply SW128 via per-thread-constant XOR (row%8 == g).
// B: cp.async (384 chunks/stage) into padded stride-104 layout.
// 4 stages, 32 ksteps of BK=32 (2x k16).
// =====================================================================
#define AT_STGB 23552              // stage stride bytes (A 16384 + B 6656, 1024-mult)
#define AT_BOFF 16384
#define ATTN_SMEM (2048 + 4*AT_STGB)   // 96256 B

__global__ void __launch_bounds__(256, 2) attn_kernel(
    const __grid_constant__ CUtensorMap tmap)
{
    extern __shared__ char smraw[];
    char* hdr = (char*)(((uintptr_t)smraw + 1023) & ~(uintptr_t)1023);
    char* datap = hdr + 1024;
    const uint32_t hdr_s = (uint32_t)__cvta_generic_to_shared(hdr);
    const uint32_t data_s = hdr_s + 1024;

    const int mt = blockIdx.x, bh = blockIdx.y, s = blockIdx.z;
    const int sbh = s*64 + bh;
    const int rowbase = sbh*1024 + mt*128;
    const uint32_t* vp = (const uint32_t*)g_vph + (size_t)sbh * 512 * 96;

    const int tid = threadIdx.x;
    const int warp = tid >> 5, lane = tid & 31;
    const int wm = warp >> 1, wn = warp & 1;
    const int g = lane >> 2, tg = lane & 3;

    if (tid == 0) {
        #pragma unroll
        for (int p = 0; p < 4; p++) MBAR_INIT(hdr_s + p*8, 1);
    }
    __syncthreads();

    // B load coords (384 chunks over 256 threads)
    const uint32_t* bsrcp[2]; uint32_t bdst[2]; bool bval[2];
    #pragma unroll
    for (int t = 0; t < 2; t++) {
        int c = tid + t*256;
        bval[t] = (c < 384);
        int pair = c / 24, off = c % 24;
        bsrcp[t] = vp + pair*96 + off*4;
        bdst[t] = data_s + AT_BOFF + (uint32_t)(pair*104 + off*4) * 4;
    }

    auto load_stage = [&](int ks, int st) {
        const uint32_t sofs = st * AT_STGB;
        if (tid == 0) {
            MBAR_EXPECT(hdr_s + st*8, 16384);
            asm volatile(
                "cp.async.bulk.tensor.2d.shared::cta.global.tile.mbarrier::complete_tx::bytes "
                "[%0], [%1, {%2, %3}], [%4];"
                :: "r"(data_s + sofs), "l"(&tmap), "r"(ks*32), "r"(rowbase),
                   "r"(hdr_s + st*8) : "memory");
        }
        const int bofs = ks * 16 * 96;   // u32
        #pragma unroll
        for (int t = 0; t < 2; t++)
            if (bval[t]) cpa16(bdst[t] + sofs, bsrcp[t] + bofs);
        CP_COMMIT();
    };

    // prologue: 4 stages
    #pragma unroll
    for (int p = 0; p < 4; p++) load_stage(p, p);

    // SW128 per-thread column byte offsets (row % 8 == g for all our rows)
    uint32_t cx[2][2];
    #pragma unroll
    for (int kk = 0; kk < 2; kk++)
        #pragma unroll
        for (int ss = 0; ss < 2; ss++)
            cx[kk][ss] = (uint32_t)((kk*64 + tg*8 + ss*32) ^ (g << 4));

    float acc[2][6][4];
    #pragma unroll
    for (int i = 0; i < 2; i++)
        #pragma unroll
        for (int j = 0; j < 6; j++)
            #pragma unroll
            for (int k = 0; k < 4; k++) acc[i][j][k] = 0.f;

    for (int ks = 0; ks < 32; ks++) {
        const int st = ks & 3;
        MBAR_WAIT(hdr_s + st*8, (ks >> 2) & 1);
        if      (ks <= 28) CP_WAIT(3);
        else if (ks == 29) CP_WAIT(2);
        else if (ks == 30) CP_WAIT(1);
        else               CP_WAIT(0);
        __syncthreads();

        const char* Ad = datap + st * AT_STGB;
        const uint32_t* Bd = (const uint32_t*)(Ad + AT_BOFF);
        #pragma unroll
        for (int kk = 0; kk < 2; kk++) {
            uint32_t a[2][4];
            #pragma unroll
            for (int mi = 0; mi < 2; mi++) {
                const char* Ar = Ad + (wm*32 + mi*16 + g) * 128;
                float2 p0 = *(const float2*)(Ar + cx[kk][0]);
                float2 p1 = *(const float2*)(Ar + 1024 + cx[kk][0]);
                float2 p2 = *(const float2*)(Ar + cx[kk][1]);
                float2 p3 = *(const float2*)(Ar + 1024 + cx[kk][1]);
                a[mi][0] = pack2(p0.x, p0.y);
                a[mi][1] = pack2(p1.x, p1.y);
                a[mi][2] = pack2(p2.x, p2.y);
                a[mi][3] = pack2(p3.x, p3.y);
            }
            #pragma unroll
            for (int nj = 0; nj < 6; nj++) {
                int j = wn*48 + nj*8 + g;
                uint32_t b[2] = { Bd[(kk*8 + tg)*104 + j], Bd[(kk*8 + tg + 4)*104 + j] };
                #pragma unroll
                for (int mi = 0; mi < 2; mi++) mma16(acc[mi][nj], a[mi], b);
            }
        }
        __syncthreads();
        if (ks + 4 < 32) load_stage(ks + 4, st);
    }

    // epilogue: pack fp16 pairs (cols j,j+1 = pairs along proj1's K) + scatter
    const int b = bh >> 3, h = bh & 7;
    uint32_t* aop = (uint32_t*)g_aoh + ((size_t)(s*NBAT + b) * NTOK) * 384;
    #pragma unroll
    for (int mi = 0; mi < 2; mi++)
        #pragma unroll
        for (int nj = 0; nj < 6; nj++) {
            const int j = wn*48 + nj*8 + 2*tg;
            const int l = j >> 5, c = j & 31;
            #pragma unroll
            for (int half = 0; half < 2; half++) {
                const int row = mt*128 + wm*32 + mi*16 + g + half*8;
                uint32_t v = pack2(acc[mi][nj][half*2], acc[mi][nj][half*2+1]);
                aop[(size_t)row*384 + l*128 + h*16 + (c >> 1)] = v;
            }
        }
}

// =====================================================================
typedef CUresult (*tmap_encode_t)(
    CUtensorMap*, CUtensorMapDataType, cuuint32_t, void*,
    const cuuint64_t*, const cuuint64_t*, const cuuint32_t*, const cuuint32_t*,
    CUtensorMapInterleave, CUtensorMapSwizzle, CUtensorMapL2promotion,
    CUtensorMapFloatOOBfill);

extern "C" void kernel_launch(void* const* d_in, const int* in_sizes, int n_in,
                              void* d_out, int out_size)
{
    const float* att  = (const float*)d_in[0];
    const float* equ1 = (const float*)d_in[1];
    const float* equ2 = (const float*)d_in[2];
    const float* Wv   = (const float*)d_in[3];
    const float* Wo   = (const float*)d_in[4];
    float* out = (float*)d_out;

    // tensormap for att: 2D (x=1024 f32, y=131072 rows), box (32,128), SW128
    static CUtensorMap tmap;
    tmap_encode_t enc = nullptr;
    cudaDriverEntryPointQueryResult qres;
    cudaGetDriverEntryPointByVersion("cuTensorMapEncodeTiled", (void**)&enc,
                                     12000, cudaEnableDefault, &qres);
    cuuint64_t dims[2]    = { 1024, 2ull*64*1024 };
    cuuint64_t strides[1] = { NTOK * sizeof(float) };
    cuuint32_t box[2]     = { 32, 128 };
    cuuint32_t estr[2]    = { 1, 1 };
    enc(&tmap, CU_TENSOR_MAP_DATA_TYPE_FLOAT32, 2, (void*)att,
        dims, strides, box, estr,
        CU_TENSOR_MAP_INTERLEAVE_NONE, CU_TENSOR_MAP_SWIZZLE_128B,
        CU_TENSOR_MAP_L2_PROMOTION_L2_128B, CU_TENSOR_MAP_FLOAT_OOB_FILL_NONE);

    const int P0_SMEM = 3 * (128*36 + 64*20) * 4;   // 70656
    const int P1_SMEM = 3 * (128*20 + 64*20) * 4;   // 46080
    cudaFuncSetAttribute(proj_kernel<0>, cudaFuncAttributeMaxDynamicSharedMemorySize, P0_SMEM);
    cudaFuncSetAttribute(proj_kernel<1>, cudaFuncAttributeMaxDynamicSharedMemorySize, P1_SMEM);
    cudaFuncSetAttribute(attn_kernel, cudaFuncAttributeMaxDynamicSharedMemorySize, ATTN_SMEM);

    wprep_kernel<<<CH*CH/256, 256>>>(Wv, Wo);
    proj_kernel<0><<<dim3(RTOT/128, CH/64, 2), 256, P0_SMEM>>>(equ1, equ2, nullptr);
    attn_kernel<<<dim3(NTOK/128, NBAT*HEADS, 2), 256, ATTN_SMEM>>>(tmap);
    proj_kernel<1><<<dim3(RTOT/128, CH/64, 2), 256, P1_SMEM>>>(equ1, equ2, out);
}

// round 8
// speedup vs baseline: 4.5398x; 1.0015x over previous
#include <cuda.h>
#include <cuda_runtime.h>
#include <cuda_fp16.h>
#include <cstdint>

#define HEADS 8
#define NBAT  8
#define NTOK  1024
#define NL    3
#define CH    256
#define RTOT  (NBAT*NTOK*NL)   // 24576 rows per stream

// ---------------- scratch (device globals: allocation-free) ----------------
// v pair-interleaved per (s,b,h): [m/2=512][lc=96][2]  (low half = even m)
__device__ __align__(256) __half g_vph[2u*64u*512u*96u*2u];
// attout fp16: [s][(b,n)][l*256 + h*32 + c]  (768 per row)
__device__ __align__(256) __half g_aoh[2u*NBAT*NTOK*NL*CH];
// weights fp16 row-major [j][256]: [0:64K)=Wv, [64K:128K)=Wo
__device__ __align__(256) __half g_Wh[2*CH*CH];

// ---------------- helpers ----------------
__device__ __forceinline__ void mma16(float* d, const uint32_t* a, const uint32_t* b) {
    asm("mma.sync.aligned.m16n8k16.row.col.f32.f16.f16.f32 "
        "{%0,%1,%2,%3}, {%4,%5,%6,%7}, {%8,%9}, {%0,%1,%2,%3};"
        : "+f"(d[0]), "+f"(d[1]), "+f"(d[2]), "+f"(d[3])
        : "r"(a[0]), "r"(a[1]), "r"(a[2]), "r"(a[3]), "r"(b[0]), "r"(b[1]));
}
__device__ __forceinline__ uint32_t pack2(float lo, float hi) {
    uint32_t r; asm("cvt.rn.f16x2.f32 %0, %1, %2;" : "=r"(r) : "f"(hi), "f"(lo)); return r;
}
__device__ __forceinline__ void cpa16(uint32_t sdst, const void* gsrc) {
    asm volatile("cp.async.cg.shared.global [%0], [%1], 16;" :: "r"(sdst), "l"(gsrc));
}
#define CP_COMMIT() asm volatile("cp.async.commit_group;")
#define CP_WAIT(n)  asm volatile("cp.async.wait_group %0;" :: "n"(n))
#define MBAR_INIT(a, c) \
    asm volatile("mbarrier.init.shared.b64 [%0], %1;" :: "r"((uint32_t)(a)), "r"((uint32_t)(c)) : "memory")
#define MBAR_EXPECT(a, b) \
    asm volatile("mbarrier.arrive.expect_tx.shared.b64 _, [%0], %1;" :: "r"((uint32_t)(a)), "r"((uint32_t)(b)) : "memory")
#define MBAR_WAIT(mb, ph) do { \
    uint32_t _m = (uint32_t)(mb), _p = (uint32_t)(ph), _d; \
    asm volatile("{\n\t.reg .pred p;\n\t" \
        "mbarrier.try_wait.parity.acquire.cta.shared::cta.b64 p, [%1], %2;\n\t" \
        "selp.b32 %0, 1, 0, p;\n\t}" : "=r"(_d) : "r"(_m), "r"(_p) : "memory"); \
    if (!_d) { \
        asm volatile("{\n\t.reg .pred P1;\n\t" \
            "WL_%=:\n\t" \
            "mbarrier.try_wait.parity.acquire.cta.shared::cta.b64 P1, [%0], %1, 0x989680;\n\t" \
            "@P1 bra.uni WD_%=;\n\tbra.uni WL_%=;\n\tWD_%=:\n\t}" \
            :: "r"(_m), "r"(_p) : "memory"); \
    } \
} while(0)

// =====================================================================
// W prep: fp16 weights
// =====================================================================
__global__ void wprep_kernel(const float* __restrict__ Wv, const float* __restrict__ Wo) {
    int i = blockIdx.x * 256 + threadIdx.x;
    g_Wh[i]         = __float2half_rn(Wv[i]);
    g_Wh[CH*CH + i] = __float2half_rn(Wo[i]);
}

// =====================================================================
// proj: MODE 0: A=equ f32 (cvt at frag load), W=Wv -> g_vph (pair scatter)
//       MODE 1: A=g_aoh fp16,                W=Wo -> out f32 + residual
// Tile 128x64, BK=32 (2x k16), K=256 -> 8 ksteps, 3-stage cp.async.
// =====================================================================
template<int MODE>
__global__ void __launch_bounds__(256, 3) proj_kernel(
    const float* __restrict__ equ1, const float* __restrict__ equ2,
    float* __restrict__ out)
{
    constexpr int ASTR = (MODE == 0) ? 36 : 20;   // u32 per A row in smem
    constexpr int STGU = 128*ASTR + 64*20;        // u32 per stage

    extern __shared__ uint32_t ps[];
    const uint32_t smem_b = (uint32_t)__cvta_generic_to_shared(ps);

    const int s = blockIdx.z;
    const int rbase = blockIdx.x * 128;
    const int jbase = blockIdx.y * 64;
    const int tid = threadIdx.x;
    const int warp = tid >> 5, lane = tid & 31;
    const int wm = warp >> 1, wn = warp & 1;
    const int g = lane >> 2, tg = lane & 3;

    const __half* Wbase = g_Wh + (MODE ? CH*CH : 0) + (size_t)jbase * CH;

    // A load coords
    const float* asrcf[4];
    const __half* asrch[2];
    uint32_t adst[4];
    if constexpr (MODE == 0) {
        const float* Af = (s ? equ2 : equ1) + (size_t)rbase * CH;
        #pragma unroll
        for (int t = 0; t < 4; t++) {
            int c = tid + t*256;
            int row = c >> 3, off = c & 7;
            asrcf[t] = Af + (size_t)row*CH + off*4;
            adst[t] = (uint32_t)(row*ASTR + off*4) * 4;
        }
    } else {
        const __half* Ah = g_aoh + (size_t)s * RTOT * CH;
        #pragma unroll
        for (int t = 0; t < 2; t++) {
            int c = tid + t*256;
            int row = c >> 2, off = c & 3;
            int r = rbase + row;
            size_t rofs = (size_t)(r/3)*768 + (size_t)(r%3)*256;
            asrch[t] = Ah + rofs + off*8;
            adst[t] = (uint32_t)(row*ASTR + off*4) * 4;
        }
    }
    const __half* wsrc = Wbase + (size_t)(tid >> 2)*CH + (tid & 3)*8;
    const uint32_t wdst = (uint32_t)(128*ASTR + (tid >> 2)*20 + (tid & 3)*4) * 4;

    auto load_stage = [&](int ks, int st) {
        const uint32_t sb = smem_b + st * STGU * 4;
        const int kb = ks * 32;
        if constexpr (MODE == 0) {
            #pragma unroll
            for (int t = 0; t < 4; t++) cpa16(sb + adst[t], asrcf[t] + kb);
        } else {
            #pragma unroll
            for (int t = 0; t < 2; t++) cpa16(sb + adst[t], asrch[t] + kb);
        }
        cpa16(sb + wdst, wsrc + kb);
        CP_COMMIT();
    };

    float acc[2][4][4];
    #pragma unroll
    for (int i = 0; i < 2; i++)
        #pragma unroll
        for (int j = 0; j < 4; j++)
            #pragma unroll
            for (int k = 0; k < 4; k++) acc[i][j][k] = 0.f;

    load_stage(0, 0);
    load_stage(1, 1);
    int st = 0;
    for (int ks = 0; ks < 8; ks++) {
        if (ks + 2 < 8) load_stage(ks + 2, (ks + 2) % 3);
        if      (ks <= 5) CP_WAIT(2);
        else if (ks == 6) CP_WAIT(1);
        else              CP_WAIT(0);
        __syncthreads();

        const uint32_t* Ad = ps + st * STGU;
        const uint32_t* Wd = Ad + 128*ASTR;
        #pragma unroll
        for (int kk = 0; kk < 2; kk++) {
            uint32_t a[2][4];
            #pragma unroll
            for (int mi = 0; mi < 2; mi++) {
                int r = wm*32 + mi*16 + g;
                if constexpr (MODE == 0) {
                    const float* Adf = (const float*)Ad;
                    float2 p0 = *(const float2*)(Adf + r*ASTR + kk*16 + 2*tg);
                    float2 p1 = *(const float2*)(Adf + (r+8)*ASTR + kk*16 + 2*tg);
                    float2 p2 = *(const float2*)(Adf + r*ASTR + kk*16 + 2*tg + 8);
                    float2 p3 = *(const float2*)(Adf + (r+8)*ASTR + kk*16 + 2*tg + 8);
                    a[mi][0] = pack2(p0.x, p0.y);
                    a[mi][1] = pack2(p1.x, p1.y);
                    a[mi][2] = pack2(p2.x, p2.y);
                    a[mi][3] = pack2(p3.x, p3.y);
                } else {
                    a[mi][0] = Ad[r*ASTR + kk*8 + tg];
                    a[mi][1] = Ad[(r+8)*ASTR + kk*8 + tg];
                    a[mi][2] = Ad[r*ASTR + kk*8 + tg + 4];
                    a[mi][3] = Ad[(r+8)*ASTR + kk*8 + tg + 4];
                }
            }
            #pragma unroll
            for (int nj = 0; nj < 4; nj++) {
                int j = wn*32 + nj*8 + g;
                uint32_t b[2] = { Wd[j*20 + kk*8 + tg], Wd[j*20 + kk*8 + tg + 4] };
                #pragma unroll
                for (int mi = 0; mi < 2; mi++) mma16(acc[mi][nj], a[mi], b);
            }
        }
        __syncthreads();
        st++; if (st == 3) st = 0;
    }

    #pragma unroll
    for (int mi = 0; mi < 2; mi++)
        #pragma unroll
        for (int nj = 0; nj < 4; nj++) {
            const int j = jbase + wn*32 + nj*8 + 2*tg;
            #pragma unroll
            for (int half = 0; half < 2; half++) {
                const int r = rbase + wm*32 + mi*16 + g + half*8;
                float v0 = acc[mi][nj][half*2], v1 = acc[mi][nj][half*2+1];
                if (MODE == 0) {
                    int b = r / 3072, rem = r % 3072;
                    int m = rem / 3, l = rem % 3;
                    int h = j >> 5, c = j & 31;
                    int sbh = s*64 + b*8 + h;
                    size_t hw = (((size_t)sbh*512 + (m>>1))*96 + l*32 + c)*2 + (m & 1);
                    g_vph[hw]     = __float2half_rn(v0);
                    g_vph[hw + 2] = __float2half_rn(v1);
                } else {
                    const float* R = s ? equ2 : equ1;
                    size_t o = (size_t)r*CH + j;
                    float2 rr = *(const float2*)&R[o];
                    float2 w = make_float2(v0 + rr.x, v1 + rr.y);
                    *(float2*)&out[(size_t)s*RTOT*CH + o] = w;
                }
            }
        }
}

// =====================================================================
// attn: per (s,bh,mt): aoh(128 x 96) = att(128x1024) @ v(1024x96), fp16 MMA
// A: 2D TMA (box 32x128 f32, SW128) -> one UTMALDG per stage, mbarrier tx.
//    Frag loads apply SW128 via per-thread-constant XOR (row%8 == g).
// B: cp.async (384 chunks/stage) into padded stride-104 layout.
// 4 stages, 32 ksteps of BK=32 (2x k16).
// =====================================================================
#define AT_STGB 23552              // stage stride bytes (A 16384 + B 6656, 1024-mult)
#define AT_BOFF 16384
#define ATTN_SMEM (2048 + 4*AT_STGB)   // 96256 B

__global__ void __launch_bounds__(256, 2) attn_kernel(
    const __grid_constant__ CUtensorMap tmap)
{
    extern __shared__ char smraw[];
    char* hdr = (char*)(((uintptr_t)smraw + 1023) & ~(uintptr_t)1023);
    char* datap = hdr + 1024;
    const uint32_t hdr_s = (uint32_t)__cvta_generic_to_shared(hdr);
    const uint32_t data_s = hdr_s + 1024;

    const int mt = blockIdx.x, bh = blockIdx.y, s = blockIdx.z;
    const int sbh = s*64 + bh;
    const int rowbase = sbh*1024 + mt*128;
    const uint32_t* vp = (const uint32_t*)g_vph + (size_t)sbh * 512 * 96;

    const int tid = threadIdx.x;
    const int warp = tid >> 5, lane = tid & 31;
    const int wm = warp >> 1, wn = warp & 1;
    const int g = lane >> 2, tg = lane & 3;

    if (tid == 0) {
        #pragma unroll
        for (int p = 0; p < 4; p++) MBAR_INIT(hdr_s + p*8, 1);
    }
    __syncthreads();

    // B load coords (384 chunks over 256 threads)
    const uint32_t* bsrcp[2]; uint32_t bdst[2]; bool bval[2];
    #pragma unroll
    for (int t = 0; t < 2; t++) {
        int c = tid + t*256;
        bval[t] = (c < 384);
        int pair = c / 24, off = c % 24;
        bsrcp[t] = vp + pair*96 + off*4;
        bdst[t] = data_s + AT_BOFF + (uint32_t)(pair*104 + off*4) * 4;
    }

    auto load_stage = [&](int ks, int st) {
        const uint32_t sofs = st * AT_STGB;
        if (tid == 0) {
            MBAR_EXPECT(hdr_s + st*8, 16384);
            asm volatile(
                "cp.async.bulk.tensor.2d.shared::cta.global.tile.mbarrier::complete_tx::bytes "
                "[%0], [%1, {%2, %3}], [%4];"
                :: "r"(data_s + sofs), "l"(&tmap), "r"(ks*32), "r"(rowbase),
                   "r"(hdr_s + st*8) : "memory");
        }
        const int bofs = ks * 16 * 96;   // u32
        #pragma unroll
        for (int t = 0; t < 2; t++)
            if (bval[t]) cpa16(bdst[t] + sofs, bsrcp[t] + bofs);
        CP_COMMIT();
    };

    // prologue: 4 stages
    #pragma unroll
    for (int p = 0; p < 4; p++) load_stage(p, p);

    // SW128 per-thread column byte offsets (row % 8 == g for all our rows)
    uint32_t cx[2][2];
    #pragma unroll
    for (int kk = 0; kk < 2; kk++)
        #pragma unroll
        for (int ss = 0; ss < 2; ss++)
            cx[kk][ss] = (uint32_t)((kk*64 + tg*8 + ss*32) ^ (g << 4));

    float acc[2][6][4];
    #pragma unroll
    for (int i = 0; i < 2; i++)
        #pragma unroll
        for (int j = 0; j < 6; j++)
            #pragma unroll
            for (int k = 0; k < 4; k++) acc[i][j][k] = 0.f;

    for (int ks = 0; ks < 32; ks++) {
        const int st = ks & 3;
        MBAR_WAIT(hdr_s + st*8, (ks >> 2) & 1);
        if      (ks <= 28) CP_WAIT(3);
        else if (ks == 29) CP_WAIT(2);
        else if (ks == 30) CP_WAIT(1);
        else               CP_WAIT(0);
        __syncthreads();

        const char* Ad = datap + st * AT_STGB;
        const uint32_t* Bd = (const uint32_t*)(Ad + AT_BOFF);
        #pragma unroll
        for (int kk = 0; kk < 2; kk++) {
            uint32_t a[2][4];
            #pragma unroll
            for (int mi = 0; mi < 2; mi++) {
                const char* Ar = Ad + (wm*32 + mi*16 + g) * 128;
                float2 p0 = *(const float2*)(Ar + cx[kk][0]);
                float2 p1 = *(const float2*)(Ar + 1024 + cx[kk][0]);
                float2 p2 = *(const float2*)(Ar + cx[kk][1]);
                float2 p3 = *(const float2*)(Ar + 1024 + cx[kk][1]);
                a[mi][0] = pack2(p0.x, p0.y);
                a[mi][1] = pack2(p1.x, p1.y);
                a[mi][2] = pack2(p2.x, p2.y);
                a[mi][3] = pack2(p3.x, p3.y);
            }
            #pragma unroll
            for (int nj = 0; nj < 6; nj++) {
                int j = wn*48 + nj*8 + g;
                uint32_t b[2] = { Bd[(kk*8 + tg)*104 + j], Bd[(kk*8 + tg + 4)*104 + j] };
                #pragma unroll
                for (int mi = 0; mi < 2; mi++) mma16(acc[mi][nj], a[mi], b);
            }
        }
        __syncthreads();
        if (ks + 4 < 32) load_stage(ks + 4, st);
    }

    // epilogue: pack fp16 pairs (cols j,j+1 = pairs along proj1's K) + scatter
    const int b = bh >> 3, h = bh & 7;
    uint32_t* aop = (uint32_t*)g_aoh + ((size_t)(s*NBAT + b) * NTOK) * 384;
    #pragma unroll
    for (int mi = 0; mi < 2; mi++)
        #pragma unroll
        for (int nj = 0; nj < 6; nj++) {
            const int j = wn*48 + nj*8 + 2*tg;
            const int l = j >> 5, c = j & 31;
            #pragma unroll
            for (int half = 0; half < 2; half++) {
                const int row = mt*128 + wm*32 + mi*16 + g + half*8;
                uint32_t v = pack2(acc[mi][nj][half*2], acc[mi][nj][half*2+1]);
                aop[(size_t)row*384 + l*128 + h*16 + (c >> 1)] = v;
            }
        }
}

// =====================================================================
typedef CUresult (*tmap_encode_t)(
    CUtensorMap*, CUtensorMapDataType, cuuint32_t, void*,
    const cuuint64_t*, const cuuint64_t*, const cuuint32_t*, const cuuint32_t*,
    CUtensorMapInterleave, CUtensorMapSwizzle, CUtensorMapL2promotion,
    CUtensorMapFloatOOBfill);

extern "C" void kernel_launch(void* const* d_in, const int* in_sizes, int n_in,
                              void* d_out, int out_size)
{
    const float* att  = (const float*)d_in[0];
    const float* equ1 = (const float*)d_in[1];
    const float* equ2 = (const float*)d_in[2];
    const float* Wv   = (const float*)d_in[3];
    const float* Wo   = (const float*)d_in[4];
    float* out = (float*)d_out;

    // tensormap for att: 2D (x=1024 f32, y=131072 rows), box (32,128), SW128
    static CUtensorMap tmap;
    tmap_encode_t enc = nullptr;
    cudaDriverEntryPointQueryResult qres;
    cudaGetDriverEntryPointByVersion("cuTensorMapEncodeTiled", (void**)&enc,
                                     12000, cudaEnableDefault, &qres);
    cuuint64_t dims[2]    = { 1024, 2ull*64*1024 };
    cuuint64_t strides[1] = { NTOK * sizeof(float) };
    cuuint32_t box[2]     = { 32, 128 };
    cuuint32_t estr[2]    = { 1, 1 };
    enc(&tmap, CU_TENSOR_MAP_DATA_TYPE_FLOAT32, 2, (void*)att,
        dims, strides, box, estr,
        CU_TENSOR_MAP_INTERLEAVE_NONE, CU_TENSOR_MAP_SWIZZLE_128B,
        CU_TENSOR_MAP_L2_PROMOTION_L2_128B, CU_TENSOR_MAP_FLOAT_OOB_FILL_NONE);

    const int P0_SMEM = 3 * (128*36 + 64*20) * 4;   // 70656
    const int P1_SMEM = 3 * (128*20 + 64*20) * 4;   // 46080
    cudaFuncSetAttribute(proj_kernel<0>, cudaFuncAttributeMaxDynamicSharedMemorySize, P0_SMEM);
    cudaFuncSetAttribute(proj_kernel<1>, cudaFuncAttributeMaxDynamicSharedMemorySize, P1_SMEM);
    cudaFuncSetAttribute(attn_kernel, cudaFuncAttributeMaxDynamicSharedMemorySize, ATTN_SMEM);

    wprep_kernel<<<CH*CH/256, 256>>>(Wv, Wo);
    proj_kernel<0><<<dim3(RTOT/128, CH/64, 2), 256, P0_SMEM>>>(equ1, equ2, nullptr);
    attn_kernel<<<dim3(NTOK/128, NBAT*HEADS, 2), 256, ATTN_SMEM>>>(tmap);
    proj_kernel<1><<<dim3(RTOT/128, CH/64, 2), 256, P1_SMEM>>>(equ1, equ2, out);
}